// round 11
// baseline (speedup 1.0000x reference)
#include <cuda_runtime.h>
#include <math.h>

#define CC 256
#define TT 4096
#define BB 8
#define BC (BB*CC)
#define NPREP 12
#define ALPHA 0.8187307530779818f
#define ONE_M_ALPHA 0.1812692469220182f
#define A8 0.20189651799465540f   /* ALPHA^8 = exp(-1.6) */

// Effective-filter coefficients (scalar), already * (1-alpha)
__device__ float g_E[CC][3][9];
__device__ float g_beP[CC][3];     // bias partials; m=0 slot includes bred
__device__ int g_done;             // prep blocks completed (0..NPREP)
__device__ int g_cnt[BB];          // lif blocks completed per batch
__device__ int g_tcnt;             // tail blocks completed

__device__ __forceinline__ int ldcg_int(const int* p) {
    int v; asm volatile("ld.global.cg.b32 %0, [%1];" : "=r"(v) : "l"(p)); return v;
}
__device__ __forceinline__ void prefetch_l2(const void* p) {
    asm volatile("prefetch.global.L2 [%0];" :: "l"(p));
}

__global__ void __launch_bounds__(512, 3) mono_kernel(
        const float* __restrict__ x,
        const float* __restrict__ w3, const float* __restrict__ b3,
        const float* __restrict__ w5, const float* __restrict__ b5,
        const float* __restrict__ w9, const float* __restrict__ b9,
        const float* __restrict__ wred, const float* __restrict__ bred,
        const float* __restrict__ lat_scale,
        const float* __restrict__ OG, const float* __restrict__ bias,
        const float* __restrict__ W1, const float* __restrict__ b1,
        const float* __restrict__ W2, const float* __restrict__ b2,
        float* __restrict__ out) {
    __shared__ float sE[27];
    __shared__ float swa[16], swb[16];
    __shared__ float s_scale;
    __shared__ int s_first;
    __shared__ float4 sact4[64];
    __shared__ float smix[256];
    __shared__ float sh[128];
    __shared__ float sp[2048];

    int tid  = threadIdx.x;
    int lane = tid & 31;
    int wrp  = tid >> 5;
    int bid  = blockIdx.x;

    // ================= tail blocks =================
    if (bid >= BC) {
        int b = bid - BC;
        // prefetch all MLP weights into L2 while lif finishes
        for (int i = tid; i < 2048; i += 512) prefetch_l2((const char*)OG + i * 128);
        for (int i = tid; i < 1024; i += 512) prefetch_l2((const char*)W1 + i * 128);
        for (int i = tid; i < 1024; i += 512) prefetch_l2((const char*)W2 + i * 128);
        if (tid == 0) { while (ldcg_int(&g_cnt[b]) != CC) __nanosleep(64); }
        __syncthreads();

        if (tid < 64) sact4[tid] = __ldcg(((const float4*)(out + 2 * BC + b * CC)) + tid);
        __syncthreads();

        // mix: 16 warps x 16 outputs
        const float4* OG4 = (const float4*)OG;
        float4 a0 = sact4[lane];
        float4 a1 = sact4[32 + lane];
        #pragma unroll 4
        for (int oo = 0; oo < 16; oo++) {
            int i = wrp * 16 + oo;
            float4 g0 = OG4[i * 64 + lane];
            float4 g1 = OG4[i * 64 + 32 + lane];
            float acc = g0.x * a0.x;
            acc = fmaf(g0.y, a0.y, acc);
            acc = fmaf(g0.z, a0.z, acc);
            acc = fmaf(g0.w, a0.w, acc);
            acc = fmaf(g1.x, a1.x, acc);
            acc = fmaf(g1.y, a1.y, acc);
            acc = fmaf(g1.z, a1.z, acc);
            acc = fmaf(g1.w, a1.w, acc);
            #pragma unroll
            for (int s = 16; s > 0; s >>= 1) acc += __shfl_xor_sync(0xffffffffu, acc, s);
            if (lane == 0) smix[i] = acc + bias[i];
        }
        __syncthreads();

        // h: 16 j-chunks of 16; thread -> 4 cols
        {
            const float4* W14 = (const float4*)W1;
            int il = tid & 31;
            int ch = tid >> 5;
            float4 acc = make_float4(0.f, 0.f, 0.f, 0.f);
            #pragma unroll 4
            for (int jj = 0; jj < 16; jj++) {
                int j = ch * 16 + jj;
                float mj = smix[j];
                float4 wr = W14[j * 32 + il];
                acc.x = fmaf(mj, wr.x, acc.x);
                acc.y = fmaf(mj, wr.y, acc.y);
                acc.z = fmaf(mj, wr.z, acc.z);
                acc.w = fmaf(mj, wr.w, acc.w);
            }
            ((float4*)sp)[ch * 32 + il] = acc;
        }
        __syncthreads();
        if (tid < 128) {
            float s = b1[tid];
            #pragma unroll
            for (int ch = 0; ch < 16; ch++) s += sp[ch * 128 + tid];
            sh[tid] = fmaxf(s, 0.f);
        }
        __syncthreads();

        // pred: 8 k-chunks of 16; thread -> 4 cols
        {
            const float4* W24 = (const float4*)W2;
            int il = tid & 63;
            int ch = tid >> 6;
            float4 acc = make_float4(0.f, 0.f, 0.f, 0.f);
            #pragma unroll 4
            for (int kk = 0; kk < 16; kk++) {
                int k = ch * 16 + kk;
                float hk = sh[k];
                float4 wr = W24[k * 64 + il];
                acc.x = fmaf(hk, wr.x, acc.x);
                acc.y = fmaf(hk, wr.y, acc.y);
                acc.z = fmaf(hk, wr.z, acc.z);
                acc.w = fmaf(hk, wr.w, acc.w);
            }
            ((float4*)sp)[ch * 64 + il] = acc;
        }
        __syncthreads();
        if (tid < 256) {
            float r = b2[tid];
            #pragma unroll
            for (int ch = 0; ch < 8; ch++) r += sp[ch * 256 + tid];
            float spv = (r > 20.f) ? r : log1pf(expf(r));
            out[b * CC + tid] = fminf(spv, 4096.0f);
        }
        __syncthreads();
        if (tid == 0) {
            __threadfence();
            int prev = atomicAdd(&g_tcnt, 1);
            if (prev == BB - 1) {           // all lif + tail work done; reset for replay
                g_tcnt = 0;
                g_done = 0;
                #pragma unroll
                for (int i = 0; i < BB; i++) g_cnt[i] = 0;
                __threadfence();
            }
        }
        return;
    }

    // ================= prep (blocks 0..NPREP-1), once per launch =================
    if (bid < NPREP) {
        int pg  = bid * 64 + (tid >> 3);   // 0..767
        int sub = tid & 7;
        int c = pg / 3;
        int m = pg - 3 * c;
        int j0 = 18 * c + 6 * m;
        const float* w; const float* bb; int K, pc0;
        if (j0 < 6 * CC)       { w = w3; bb = b3; K = 3; pc0 = j0; }
        else if (j0 < 12 * CC) { w = w5; bb = b5; K = 5; pc0 = j0 - 6 * CC; }
        else                   { w = w9; bb = b9; K = 9; pc0 = j0 - 12 * CC; }
        int pad = (K - 1) / 2;

        float E[9];
        #pragma unroll
        for (int t = 0; t < 9; t++) E[t] = 0.f;
        float be = 0.f;
        if (sub < 6) {
            int r = sub;
            float wr = wred[c * 18 + 6 * m + r];
            be = wr * bb[pc0 + r];
            for (int u = 0; u < K; u++)
                E[4 + u - pad] = wr * w[(pc0 + r) * K + u];
        }
        #pragma unroll
        for (int s = 4; s > 0; s >>= 1) {
            #pragma unroll
            for (int t = 0; t < 9; t++) E[t] += __shfl_xor_sync(0xffffffffu, E[t], s);
            be += __shfl_xor_sync(0xffffffffu, be, s);
        }
        if (sub == 0) {
            #pragma unroll
            for (int t = 0; t < 9; t++) g_E[c][m][t] = E[t] * ONE_M_ALPHA;
            g_beP[c][m] = be * ONE_M_ALPHA + ((m == 0) ? bred[c] * ONE_M_ALPHA : 0.f);
        }
        __syncthreads();
        if (tid == 0) { __threadfence(); atomicAdd(&g_done, 1); }
    }

    // ================= gate: wait for coefficients =================
    if (tid == 0) {
        while (ldcg_int(&g_done) != NPREP) __nanosleep(32);
        s_first = TT;
        s_scale = fmaxf(lat_scale[0], 0.001f);
    }
    __syncthreads();
    int b = bid >> 8;
    int c = bid & 255;
    if (tid < 27) sE[tid] = ((const float*)g_E)[c * 27 + tid];
    __syncthreads();

    // ================= lif: 8 timesteps/thread, scalar =================
    float u[8];
    float be = g_beP[c][0] + g_beP[c][1] + g_beP[c][2];
    #pragma unroll
    for (int jj = 0; jj < 8; jj++) u[jj] = be;

    const float4 z4 = make_float4(0.f, 0.f, 0.f, 0.f);
    #pragma unroll
    for (int m = 0; m < 3; m++) {
        int xch = (3 * c + m) & 255;
        const float4* row4 = (const float4*)(x + ((size_t)(b * CC + xch)) * TT);
        float4 c0 = row4[tid * 2 + 0];
        float4 c1 = row4[tid * 2 + 1];
        float4 hp = (tid > 0)   ? row4[tid * 2 - 1] : z4;
        float4 hn = (tid < 511) ? row4[tid * 2 + 2] : z4;

        float w[16];
        w[0]=hp.x;  w[1]=hp.y;  w[2]=hp.z;  w[3]=hp.w;
        w[4]=c0.x;  w[5]=c0.y;  w[6]=c0.z;  w[7]=c0.w;
        w[8]=c1.x;  w[9]=c1.y;  w[10]=c1.z; w[11]=c1.w;
        w[12]=hn.x; w[13]=hn.y; w[14]=hn.z; w[15]=hn.w;

        #pragma unroll
        for (int t = 0; t < 9; t++) {
            float e = sE[m * 9 + t];
            #pragma unroll
            for (int jj = 0; jj < 8; jj++)
                u[jj] = fmaf(e, w[jj + t], u[jj]);
        }
    }

    float bacc = 0.f;
    #pragma unroll
    for (int jj = 0; jj < 8; jj++) bacc = fmaf(ALPHA, bacc, u[jj]);

    float a = A8, bs = bacc;
    #pragma unroll
    for (int s = 1; s < 32; s <<= 1) {
        float ao = __shfl_up_sync(0xffffffffu, a, s);
        float bo = __shfl_up_sync(0xffffffffu, bs, s);
        if (lane >= s) { bs = fmaf(a, bo, bs); a *= ao; }
    }
    if (lane == 31) { swa[wrp] = a; swb[wrp] = bs; }
    __syncthreads();

    float pb = 0.f;
    for (int ww = 0; ww < wrp; ww++) pb = fmaf(swa[ww], pb, swb[ww]);

    float ae  = __shfl_up_sync(0xffffffffu, a, 1);
    float bse = __shfl_up_sync(0xffffffffu, bs, 1);
    if (lane == 0) { ae = 1.f; bse = 0.f; }
    float V = fmaf(ae, pb, bse);

    int t0 = tid * 8;
    int ft = 0x7fffffff;
    #pragma unroll
    for (int jj = 0; jj < 8; jj++) {
        V = fmaf(ALPHA, V, u[jj]);
        if (V >= 1.0f && ft == 0x7fffffff) ft = t0 + jj;
    }
    if (ft != 0x7fffffff) atomicMin(&s_first, ft);
    __syncthreads();

    if (tid == 0) {
        float tl = (float)s_first;
        out[BC + bid] = tl;
        out[2 * BC + bid] = expf(-tl / s_scale);
        __threadfence();
        atomicAdd(&g_cnt[b], 1);
    }
}

extern "C" void kernel_launch(void* const* d_in, const int* in_sizes, int n_in,
                              void* d_out, int out_size) {
    const float* x    = (const float*)d_in[0];
    const float* w3   = (const float*)d_in[1];
    const float* b3   = (const float*)d_in[2];
    const float* w5   = (const float*)d_in[3];
    const float* b5   = (const float*)d_in[4];
    const float* w9   = (const float*)d_in[5];
    const float* b9   = (const float*)d_in[6];
    const float* wred = (const float*)d_in[7];
    const float* bred = (const float*)d_in[8];
    const float* ls   = (const float*)d_in[9];
    const float* og   = (const float*)d_in[10];
    const float* bias = (const float*)d_in[11];
    const float* W1   = (const float*)d_in[12];
    const float* b1   = (const float*)d_in[13];
    const float* W2   = (const float*)d_in[14];
    const float* b2   = (const float*)d_in[15];
    float* out = (float*)d_out;

    mono_kernel<<<BC + BB, 512>>>(x, w3, b3, w5, b5, w9, b9, wred, bred,
                                  ls, og, bias, W1, b1, W2, b2, out);
}

// round 12
// speedup vs baseline: 1.0598x; 1.0598x over previous
#include <cuda_runtime.h>
#include <math.h>

#define CC 256
#define TT 4096
#define BB 8
#define BC (BB*CC)
#define ALPHA 0.8187307530779818f
#define ONE_M_ALPHA 0.1812692469220182f
#define A8 0.20189651799465540f   /* ALPHA^8 = exp(-1.6) */

// ---------------- lif: one block per (b, c); 512 threads, 8 timesteps/thread ----------------
// Coefficients computed in-block: thread (k,u) does 2 parallel loads + smem atomicAdd.
// out layout: [0,BC) pred (by k_tail), [BC,2BC) true_latency, [2BC,3BC) act.
__global__ void __launch_bounds__(512, 3) lif_kernel(
        const float* __restrict__ x,
        const float* __restrict__ w3, const float* __restrict__ b3,
        const float* __restrict__ w5, const float* __restrict__ b5,
        const float* __restrict__ w9, const float* __restrict__ b9,
        const float* __restrict__ wred, const float* __restrict__ bred,
        const float* __restrict__ lat_scale,
        float* __restrict__ out) {
    __shared__ float sE[28];           // [27] = bias accumulator
    __shared__ float swa[16], swb[16];
    __shared__ float s_scale;
    __shared__ int s_first;

    int tid  = threadIdx.x;
    int lane = tid & 31;
    int wrp  = tid >> 5;
    int bc = blockIdx.x;
    int b  = bc >> 8;
    int c  = bc & 255;

    if (tid < 28) sE[tid] = 0.f;
    if (tid == 28) s_first = TT;
    if (tid == 29) s_scale = fmaxf(lat_scale[0], 0.001f);
    __syncthreads();

    // ---- parallel in-block coefficient computation: 162 threads, 2 loads each ----
    if (tid < 162) {
        int k = tid / 9;               // 0..17 reduce-row
        int u = tid - 9 * k;           // 0..8 tap within kernel
        int j = 18 * c + k;
        int bkt = j / 1536;            // 0,1,2
        int pc  = j - 1536 * bkt;
        const float* w  = (bkt == 0) ? w3 : (bkt == 1) ? w5 : w9;
        const float* bb = (bkt == 0) ? b3 : (bkt == 1) ? b5 : b9;
        int K   = (bkt == 0) ? 3 : (bkt == 1) ? 5 : 9;
        int pad = (K - 1) >> 1;
        int m = k / 6;
        float wr = wred[j] * ONE_M_ALPHA;
        if (u < K) atomicAdd(&sE[m * 9 + 4 + u - pad], wr * w[pc * K + u]);
        if (u == 0) atomicAdd(&sE[27], wr * bb[pc]);
    }
    if (tid == 162) atomicAdd(&sE[27], bred[c] * ONE_M_ALPHA);
    __syncthreads();

    // ---- conv: 8 timesteps/thread, halos by direct LDG (L1/L2 hits) ----
    float u[8];
    float be = sE[27];
    #pragma unroll
    for (int jj = 0; jj < 8; jj++) u[jj] = be;

    const float4 z4 = make_float4(0.f, 0.f, 0.f, 0.f);
    #pragma unroll
    for (int m = 0; m < 3; m++) {
        int xch = (3 * c + m) & 255;
        const float4* row4 = (const float4*)(x + ((size_t)(b * CC + xch)) * TT);
        float4 c0 = row4[tid * 2 + 0];
        float4 c1 = row4[tid * 2 + 1];
        float4 hp = (tid > 0)   ? row4[tid * 2 - 1] : z4;
        float4 hn = (tid < 511) ? row4[tid * 2 + 2] : z4;

        float w[16];
        w[0]=hp.x;  w[1]=hp.y;  w[2]=hp.z;  w[3]=hp.w;
        w[4]=c0.x;  w[5]=c0.y;  w[6]=c0.z;  w[7]=c0.w;
        w[8]=c1.x;  w[9]=c1.y;  w[10]=c1.z; w[11]=c1.w;
        w[12]=hn.x; w[13]=hn.y; w[14]=hn.z; w[15]=hn.w;

        #pragma unroll
        for (int t = 0; t < 9; t++) {
            float e = sE[m * 9 + t];
            #pragma unroll
            for (int jj = 0; jj < 8; jj++)
                u[jj] = fmaf(e, w[jj + t], u[jj]);
        }
    }

    // ---- segment transform V -> A8*V + bacc; two-level scan ----
    float bacc = 0.f;
    #pragma unroll
    for (int jj = 0; jj < 8; jj++) bacc = fmaf(ALPHA, bacc, u[jj]);

    float a = A8, bs = bacc;
    #pragma unroll
    for (int s = 1; s < 32; s <<= 1) {
        float ao = __shfl_up_sync(0xffffffffu, a, s);
        float bo = __shfl_up_sync(0xffffffffu, bs, s);
        if (lane >= s) { bs = fmaf(a, bo, bs); a *= ao; }
    }
    if (lane == 31) { swa[wrp] = a; swb[wrp] = bs; }
    __syncthreads();

    float pb = 0.f;
    for (int ww = 0; ww < wrp; ww++) pb = fmaf(swa[ww], pb, swb[ww]);

    float ae  = __shfl_up_sync(0xffffffffu, a, 1);
    float bse = __shfl_up_sync(0xffffffffu, bs, 1);
    if (lane == 0) { ae = 1.f; bse = 0.f; }
    float V = fmaf(ae, pb, bse);   // V at start of this thread's segment

    int t0 = tid * 8;
    int ft = 0x7fffffff;
    #pragma unroll
    for (int jj = 0; jj < 8; jj++) {
        V = fmaf(ALPHA, V, u[jj]);
        if (V >= 1.0f && ft == 0x7fffffff) ft = t0 + jj;
    }
    if (ft != 0x7fffffff) atomicMin(&s_first, ft);
    __syncthreads();

    if (tid == 0) {
        float tl = (float)s_first;
        out[BC + bc] = tl;
        out[2 * BC + bc] = expf(-tl / s_scale);
    }
}

// ---------------- fused tail: act -> mix -> h -> pred. 1024 threads per batch row ----------------
__global__ void __launch_bounds__(1024) k_tail(const float* __restrict__ OG,
                                               const float* __restrict__ bias,
                                               const float* __restrict__ W1,
                                               const float* __restrict__ b1,
                                               const float* __restrict__ W2,
                                               const float* __restrict__ b2,
                                               float* __restrict__ out) {
    __shared__ float4 sact4[64];
    __shared__ float smix[256];
    __shared__ float sh[128];
    __shared__ float sp[4096];      // 16KB: [32][128] for h, [16][256] for pred

    int b = blockIdx.x;
    int t = threadIdx.x;
    int lane = t & 31;
    int wrp  = t >> 5;              // 0..31

    if (t < 64) sact4[t] = ((const float4*)(out + 2 * BC + b * CC))[t];
    __syncthreads();

    // ---- mix: 32 warps x 8 outputs; 16 independent float4 loads per lane ----
    const float4* OG4 = (const float4*)OG;
    float4 a0 = sact4[lane];
    float4 a1 = sact4[32 + lane];
    #pragma unroll
    for (int oo = 0; oo < 8; oo++) {
        int i = wrp * 8 + oo;
        float4 g0 = OG4[i * 64 + lane];
        float4 g1 = OG4[i * 64 + 32 + lane];
        float acc = g0.x * a0.x;
        acc = fmaf(g0.y, a0.y, acc);
        acc = fmaf(g0.z, a0.z, acc);
        acc = fmaf(g0.w, a0.w, acc);
        acc = fmaf(g1.x, a1.x, acc);
        acc = fmaf(g1.y, a1.y, acc);
        acc = fmaf(g1.z, a1.z, acc);
        acc = fmaf(g1.w, a1.w, acc);
        #pragma unroll
        for (int s = 16; s > 0; s >>= 1) acc += __shfl_xor_sync(0xffffffffu, acc, s);
        if (lane == 0) smix[i] = acc + bias[i];
    }
    __syncthreads();

    // ---- h: 32 j-chunks of 8; thread -> 4 cols ----
    {
        const float4* W14 = (const float4*)W1;
        int il = t & 31;
        int ch = t >> 5;
        float4 acc = make_float4(0.f, 0.f, 0.f, 0.f);
        #pragma unroll
        for (int jj = 0; jj < 8; jj++) {
            int j = ch * 8 + jj;
            float mj = smix[j];
            float4 wr = W14[j * 32 + il];
            acc.x = fmaf(mj, wr.x, acc.x);
            acc.y = fmaf(mj, wr.y, acc.y);
            acc.z = fmaf(mj, wr.z, acc.z);
            acc.w = fmaf(mj, wr.w, acc.w);
        }
        ((float4*)sp)[ch * 32 + il] = acc;
    }
    __syncthreads();
    if (t < 128) {
        float s = b1[t];
        #pragma unroll
        for (int ch = 0; ch < 32; ch++) s += sp[ch * 128 + t];
        sh[t] = fmaxf(s, 0.f);
    }
    __syncthreads();

    // ---- pred: 16 k-chunks of 8; thread -> 4 cols ----
    {
        const float4* W24 = (const float4*)W2;
        int il = t & 63;
        int ch = t >> 6;
        float4 acc = make_float4(0.f, 0.f, 0.f, 0.f);
        #pragma unroll
        for (int kk = 0; kk < 8; kk++) {
            int k = ch * 8 + kk;
            float hk = sh[k];
            float4 wr = W24[k * 64 + il];
            acc.x = fmaf(hk, wr.x, acc.x);
            acc.y = fmaf(hk, wr.y, acc.y);
            acc.z = fmaf(hk, wr.z, acc.z);
            acc.w = fmaf(hk, wr.w, acc.w);
        }
        ((float4*)sp)[ch * 64 + il] = acc;
    }
    __syncthreads();
    if (t < 256) {
        float r = b2[t];
        #pragma unroll
        for (int ch = 0; ch < 16; ch++) r += sp[ch * 256 + t];
        float spv = (r > 20.f) ? r : log1pf(expf(r));
        out[b * CC + t] = fminf(spv, 4096.0f);
    }
}

extern "C" void kernel_launch(void* const* d_in, const int* in_sizes, int n_in,
                              void* d_out, int out_size) {
    const float* x    = (const float*)d_in[0];
    const float* w3   = (const float*)d_in[1];
    const float* b3   = (const float*)d_in[2];
    const float* w5   = (const float*)d_in[3];
    const float* b5   = (const float*)d_in[4];
    const float* w9   = (const float*)d_in[5];
    const float* b9   = (const float*)d_in[6];
    const float* wred = (const float*)d_in[7];
    const float* bred = (const float*)d_in[8];
    const float* ls   = (const float*)d_in[9];
    const float* og   = (const float*)d_in[10];
    const float* bias = (const float*)d_in[11];
    const float* W1   = (const float*)d_in[12];
    const float* b1   = (const float*)d_in[13];
    const float* W2   = (const float*)d_in[14];
    const float* b2   = (const float*)d_in[15];
    float* out = (float*)d_out;

    lif_kernel<<<BC, 512>>>(x, w3, b3, w5, b5, w9, b9, wred, bred, ls, out);
    k_tail<<<BB, 1024>>>(og, bias, W1, b1, W2, b2, out);
}